// round 4
// baseline (speedup 1.0000x reference)
#include <cuda_runtime.h>
#include <cuda_fp16.h>
#include <cuda_bf16.h>

#define N_NODES 100000
#define N_EDGES 1600000
#define F_IN 128
#define N_H 3
#define N_D 16
#define HD 48
#define NEG_SLOPE 0.2f

#define SCAN_B 256
#define NB ((N_NODES + SCAN_B - 1) / SCAN_B)   // 391

// Scratch (device globals)
__device__ float  g_feat[N_NODES * HD];     // projected features (N,48) fp32
__device__ __half g_feat_h[N_NODES * HD];   // fp16 shadow for agg gathers
__device__ float4 g_el[N_NODES];            // (el0,el1,el2,_)
__device__ float4 g_er[N_NODES];            // (er0,er1,er2,_)
__device__ float4 g_edge[N_EDGES];          // packed (src_as_float, x0, x1, x2), grouped by dst
__device__ int    g_count[N_NODES];         // in-degree
__device__ int    g_off[N_NODES];           // CSR segment start
__device__ int    g_cur[N_NODES];           // scatter cursor
__device__ int    g_bsum[NB];               // per-block count sums
__device__ int    g_bbase[NB];              // exclusive scan of block sums

// ---------------------------------------------------------------------------
// Kernel 0: zero degree counters
// ---------------------------------------------------------------------------
__global__ void k_init() {
    int i = blockIdx.x * blockDim.x + threadIdx.x;
    if (i < N_NODES) g_count[i] = 0;
}

// ---------------------------------------------------------------------------
// Kernel 1: feat = x @ W^T  (N x 48), plus el/er attention logits.
// SMEM W stored as Ws[j][k] so the inner loop uses one broadcast LDS.128
// per output column (4x fewer LDS issues than scalar).
// ---------------------------------------------------------------------------
__global__ __launch_bounds__(128) void k_gemm(const float* __restrict__ x,
                                              const float* __restrict__ W,
                                              const float* __restrict__ al,
                                              const float* __restrict__ ar)
{
    __shared__ float Ws[HD][F_IN];     // Ws[j][k] = W[j*F_IN + k]
    __shared__ float als[HD], ars[HD];
    for (int i = threadIdx.x; i < HD * F_IN; i += 128) {
        Ws[i / F_IN][i % F_IN] = W[i];
    }
    if (threadIdx.x < HD) {
        als[threadIdx.x] = al[threadIdx.x];
        ars[threadIdx.x] = ar[threadIdx.x];
    }
    __syncthreads();

    int t  = blockIdx.x * 128 + threadIdx.x;
    int n0 = 2 * t, n1 = 2 * t + 1;
    if (n0 >= N_NODES) return;
    bool has1 = (n1 < N_NODES);

    float acc0[HD], acc1[HD];
#pragma unroll
    for (int j = 0; j < HD; j++) { acc0[j] = 0.f; acc1[j] = 0.f; }

    const float4* x4 = (const float4*)x;
    int b0 = n0 * (F_IN / 4);
    int b1 = n1 * (F_IN / 4);

    for (int i = 0; i < F_IN / 4; i++) {
        float4 a = x4[b0 + i];
        float4 b = has1 ? x4[b1 + i] : make_float4(0.f, 0.f, 0.f, 0.f);
#pragma unroll
        for (int j = 0; j < HD; j++) {
            float4 w = *(const float4*)&Ws[j][4 * i];   // broadcast LDS.128
            acc0[j] = fmaf(a.x, w.x, fmaf(a.y, w.y, fmaf(a.z, w.z, fmaf(a.w, w.w, acc0[j]))));
            acc1[j] = fmaf(b.x, w.x, fmaf(b.y, w.y, fmaf(b.z, w.z, fmaf(b.w, w.w, acc1[j]))));
        }
    }

    // epilogue: logits + fp32 feat + fp16 shadow
    {
        float el[N_H], er[N_H];
#pragma unroll
        for (int h = 0; h < N_H; h++) { el[h] = 0.f; er[h] = 0.f; }
#pragma unroll
        for (int h = 0; h < N_H; h++)
#pragma unroll
            for (int d = 0; d < N_D; d++) {
                el[h] = fmaf(acc0[h * N_D + d], als[h * N_D + d], el[h]);
                er[h] = fmaf(acc0[h * N_D + d], ars[h * N_D + d], er[h]);
            }
        g_el[n0] = make_float4(el[0], el[1], el[2], 0.f);
        g_er[n0] = make_float4(er[0], er[1], er[2], 0.f);
        float4* f4 = (float4*)(g_feat + (size_t)n0 * HD);
        __half2* h2 = (__half2*)(g_feat_h + (size_t)n0 * HD);
#pragma unroll
        for (int j = 0; j < HD / 4; j++) {
            f4[j] = make_float4(acc0[4 * j], acc0[4 * j + 1], acc0[4 * j + 2], acc0[4 * j + 3]);
            h2[2 * j]     = __floats2half2_rn(acc0[4 * j],     acc0[4 * j + 1]);
            h2[2 * j + 1] = __floats2half2_rn(acc0[4 * j + 2], acc0[4 * j + 3]);
        }
    }
    if (has1) {
        float el[N_H], er[N_H];
#pragma unroll
        for (int h = 0; h < N_H; h++) { el[h] = 0.f; er[h] = 0.f; }
#pragma unroll
        for (int h = 0; h < N_H; h++)
#pragma unroll
            for (int d = 0; d < N_D; d++) {
                el[h] = fmaf(acc1[h * N_D + d], als[h * N_D + d], el[h]);
                er[h] = fmaf(acc1[h * N_D + d], ars[h * N_D + d], er[h]);
            }
        g_el[n1] = make_float4(el[0], el[1], el[2], 0.f);
        g_er[n1] = make_float4(er[0], er[1], er[2], 0.f);
        float4* f4 = (float4*)(g_feat + (size_t)n1 * HD);
        __half2* h2 = (__half2*)(g_feat_h + (size_t)n1 * HD);
#pragma unroll
        for (int j = 0; j < HD / 4; j++) {
            f4[j] = make_float4(acc1[4 * j], acc1[4 * j + 1], acc1[4 * j + 2], acc1[4 * j + 3]);
            h2[2 * j]     = __floats2half2_rn(acc1[4 * j],     acc1[4 * j + 1]);
            h2[2 * j + 1] = __floats2half2_rn(acc1[4 * j + 2], acc1[4 * j + 3]);
        }
    }
}

// ---------------------------------------------------------------------------
// Kernel 2: in-degree histogram
// ---------------------------------------------------------------------------
__global__ void k_hist(const int* __restrict__ dst) {
    int e = blockIdx.x * blockDim.x + threadIdx.x;
    if (e >= N_EDGES) return;
    atomicAdd(&g_count[dst[e]], 1);
}

// ---------------------------------------------------------------------------
// Kernel 3a: per-block sums of g_count
// ---------------------------------------------------------------------------
__global__ __launch_bounds__(SCAN_B) void k_bsum() {
    __shared__ int sh[SCAN_B];
    int i = blockIdx.x * SCAN_B + threadIdx.x;
    sh[threadIdx.x] = (i < N_NODES) ? g_count[i] : 0;
    __syncthreads();
    for (int off = SCAN_B / 2; off > 0; off >>= 1) {
        if (threadIdx.x < off) sh[threadIdx.x] += sh[threadIdx.x + off];
        __syncthreads();
    }
    if (threadIdx.x == 0) g_bsum[blockIdx.x] = sh[0];
}

// ---------------------------------------------------------------------------
// Kernel 3b: exclusive scan of block sums (single small block)
// ---------------------------------------------------------------------------
__global__ __launch_bounds__(512) void k_sscan() {
    __shared__ int sh[512];
    int t = threadIdx.x;
    sh[t] = (t < NB) ? g_bsum[t] : 0;
    __syncthreads();
    for (int off = 1; off < 512; off <<= 1) {
        int v = (t >= off) ? sh[t - off] : 0;
        __syncthreads();
        sh[t] += v;
        __syncthreads();
    }
    if (t < NB) g_bbase[t] = (t == 0) ? 0 : sh[t - 1];
}

// ---------------------------------------------------------------------------
// Kernel 3c: in-block exclusive scan + block base -> g_off, g_cur
// ---------------------------------------------------------------------------
__global__ __launch_bounds__(SCAN_B) void k_off() {
    __shared__ int sh[SCAN_B];
    int i = blockIdx.x * SCAN_B + threadIdx.x;
    int t = threadIdx.x;
    int c = (i < N_NODES) ? g_count[i] : 0;
    sh[t] = c;
    __syncthreads();
    for (int off = 1; off < SCAN_B; off <<= 1) {
        int v = (t >= off) ? sh[t - off] : 0;
        __syncthreads();
        sh[t] += v;
        __syncthreads();
    }
    if (i < N_NODES) {
        int excl = g_bbase[blockIdx.x] + sh[t] - c;
        g_off[i] = excl;
        g_cur[i] = excl;
    }
}

// ---------------------------------------------------------------------------
// Kernel 4: edge scatter — exp(leakyrelu(el[src]+er[dst])) per head,
// pack (src, x0, x1, x2) into the dst-grouped edge array.
// Max-subtraction skipped: |e| <= ~4, softmax shift-invariant (fp32-safe).
// ---------------------------------------------------------------------------
__global__ void k_scatter(const int* __restrict__ src, const int* __restrict__ dst) {
    int e = blockIdx.x * blockDim.x + threadIdx.x;
    if (e >= N_EDGES) return;
    int s = src[e], d = dst[e];
    float4 L = g_el[s];
    float4 R = g_er[d];
    float v0 = L.x + R.x, v1 = L.y + R.y, v2 = L.z + R.z;
    v0 = v0 > 0.f ? v0 : NEG_SLOPE * v0;
    v1 = v1 > 0.f ? v1 : NEG_SLOPE * v1;
    v2 = v2 > 0.f ? v2 : NEG_SLOPE * v2;
    float x0 = __expf(v0), x1 = __expf(v1), x2 = __expf(v2);
    int pos = atomicAdd(&g_cur[d], 1);
    g_edge[pos] = make_float4(__int_as_float(s), x0, x1, x2);
}

// ---------------------------------------------------------------------------
// Kernel 5: per-dst aggregation. 48 threads per node (one per output comp).
// Gathers the fp16 feat shadow (halves random L2 traffic); fp32 accumulate.
// Fused softmax-normalize + linear_comb blend (blend uses exact fp32 feat).
// ---------------------------------------------------------------------------
__global__ __launch_bounds__(192) void k_agg(const float* __restrict__ lin,
                                             float* __restrict__ out) {
    int d = blockIdx.x * 4 + threadIdx.y;
    if (d >= N_NODES) return;
    int c = threadIdx.x;        // 0..47
    int h = c >> 4;             // head index 0..2

    int beg = g_off[d];
    int cnt = g_count[d];
    int end = beg + cnt;

    float num = 0.f, den = 0.f;
#pragma unroll 2
    for (int p = beg; p < end; p++) {
        float4 pk = g_edge[p];
        int s = __float_as_int(pk.x);
        float a = (h == 0) ? pk.y : ((h == 1) ? pk.z : pk.w);
        float f = __half2float(__ldg(&g_feat_h[s * HD + c]));
        num = fmaf(a, f, num);
        den += a;
    }
    float msg = (cnt > 0) ? (num / den) : 0.f;
    float l = lin[d];
    float fd = g_feat[d * HD + c];
    out[d * HD + c] = (1.f - l) * msg + l * fd;
}

// ---------------------------------------------------------------------------
extern "C" void kernel_launch(void* const* d_in, const int* in_sizes, int n_in,
                              void* d_out, int out_size) {
    const float* x   = (const float*)d_in[0];
    const float* W   = (const float*)d_in[1];
    const float* al  = (const float*)d_in[2];
    const float* ar  = (const float*)d_in[3];
    const float* lin = (const float*)d_in[4];
    const int*   src = (const int*)d_in[5];
    const int*   dst = (const int*)d_in[6];
    float* out = (float*)d_out;

    k_init<<<(N_NODES + 255) / 256, 256>>>();
    k_gemm<<<(N_NODES + 255) / 256, 128>>>(x, W, al, ar);
    k_hist<<<(N_EDGES + 255) / 256, 256>>>(dst);
    k_bsum<<<NB, SCAN_B>>>();
    k_sscan<<<1, 512>>>();
    k_off<<<NB, SCAN_B>>>();
    k_scatter<<<(N_EDGES + 255) / 256, 256>>>(src, dst);

    dim3 aggBlock(48, 4);
    k_agg<<<(N_NODES + 3) / 4, aggBlock>>>(lin, out);
}

// round 5
// speedup vs baseline: 1.1911x; 1.1911x over previous
#include <cuda_runtime.h>
#include <cuda_bf16.h>

#define N_NODES 100000
#define N_EDGES 1600000
#define F_IN 128
#define N_H 3
#define N_D 16
#define HD 48
#define NEG_SLOPE 0.2f

#define SCAN_B 256
#define NB ((N_NODES + SCAN_B - 1) / SCAN_B)   // 391

// Scratch (device globals)
__device__ float  g_feat[N_NODES * HD];     // projected features (N,48)
__device__ float4 g_el[N_NODES];            // (el0,el1,el2,_)
__device__ float4 g_er[N_NODES];            // (er0,er1,er2,_)
__device__ float4 g_edge[N_EDGES];          // packed (src_as_float, x0, x1, x2), grouped by dst
__device__ int    g_count[N_NODES];         // in-degree
__device__ int    g_off[N_NODES];           // CSR segment start
__device__ int    g_cur[N_NODES];           // scatter cursor
__device__ int    g_bsum[NB];               // per-block count sums
__device__ int    g_bbase[NB];              // exclusive scan of block sums

// ---------------------------------------------------------------------------
// Kernel 0: zero degree counters
// ---------------------------------------------------------------------------
__global__ void k_init() {
    int i = blockIdx.x * blockDim.x + threadIdx.x;
    if (i < N_NODES) g_count[i] = 0;
}

// ---------------------------------------------------------------------------
// Kernel 1: feat = x @ W^T (N x 48) + el/er logits.
// W in SMEM as float4 rows: one broadcast LDS.128 feeds 8 FFMA.
// ---------------------------------------------------------------------------
__global__ __launch_bounds__(128) void k_gemm(const float* __restrict__ x,
                                              const float* __restrict__ W,
                                              const float* __restrict__ al,
                                              const float* __restrict__ ar)
{
    __shared__ float4 Ws4[HD][F_IN / 4];   // Ws4[j][i] = W[j*F_IN + 4i .. +3]
    __shared__ float als[HD], ars[HD];
    for (int i = threadIdx.x; i < HD * (F_IN / 4); i += 128) {
        Ws4[i / (F_IN / 4)][i % (F_IN / 4)] = ((const float4*)W)[i];
    }
    if (threadIdx.x < HD) {
        als[threadIdx.x] = al[threadIdx.x];
        ars[threadIdx.x] = ar[threadIdx.x];
    }
    __syncthreads();

    int t  = blockIdx.x * 128 + threadIdx.x;
    int n0 = 2 * t, n1 = 2 * t + 1;
    if (n0 >= N_NODES) return;
    bool has1 = (n1 < N_NODES);

    float acc0[HD], acc1[HD];
#pragma unroll
    for (int j = 0; j < HD; j++) { acc0[j] = 0.f; acc1[j] = 0.f; }

    const float4* x4 = (const float4*)x;
    int b0 = n0 * (F_IN / 4);
    int b1 = n1 * (F_IN / 4);

    for (int i = 0; i < F_IN / 4; i++) {
        float4 a = x4[b0 + i];
        float4 b = has1 ? x4[b1 + i] : make_float4(0.f, 0.f, 0.f, 0.f);
#pragma unroll
        for (int j = 0; j < HD; j++) {
            float4 w = Ws4[j][i];          // broadcast LDS.128
            acc0[j] = fmaf(a.x, w.x, fmaf(a.y, w.y, fmaf(a.z, w.z, fmaf(a.w, w.w, acc0[j]))));
            acc1[j] = fmaf(b.x, w.x, fmaf(b.y, w.y, fmaf(b.z, w.z, fmaf(b.w, w.w, acc1[j]))));
        }
    }

    {
        float el[N_H], er[N_H];
#pragma unroll
        for (int h = 0; h < N_H; h++) { el[h] = 0.f; er[h] = 0.f; }
#pragma unroll
        for (int h = 0; h < N_H; h++)
#pragma unroll
            for (int d = 0; d < N_D; d++) {
                el[h] = fmaf(acc0[h * N_D + d], als[h * N_D + d], el[h]);
                er[h] = fmaf(acc0[h * N_D + d], ars[h * N_D + d], er[h]);
            }
        g_el[n0] = make_float4(el[0], el[1], el[2], 0.f);
        g_er[n0] = make_float4(er[0], er[1], er[2], 0.f);
        float4* f4 = (float4*)(g_feat + (size_t)n0 * HD);
#pragma unroll
        for (int j = 0; j < HD / 4; j++)
            f4[j] = make_float4(acc0[4 * j], acc0[4 * j + 1], acc0[4 * j + 2], acc0[4 * j + 3]);
    }
    if (has1) {
        float el[N_H], er[N_H];
#pragma unroll
        for (int h = 0; h < N_H; h++) { el[h] = 0.f; er[h] = 0.f; }
#pragma unroll
        for (int h = 0; h < N_H; h++)
#pragma unroll
            for (int d = 0; d < N_D; d++) {
                el[h] = fmaf(acc1[h * N_D + d], als[h * N_D + d], el[h]);
                er[h] = fmaf(acc1[h * N_D + d], ars[h * N_D + d], er[h]);
            }
        g_el[n1] = make_float4(el[0], el[1], el[2], 0.f);
        g_er[n1] = make_float4(er[0], er[1], er[2], 0.f);
        float4* f4 = (float4*)(g_feat + (size_t)n1 * HD);
#pragma unroll
        for (int j = 0; j < HD / 4; j++)
            f4[j] = make_float4(acc1[4 * j], acc1[4 * j + 1], acc1[4 * j + 2], acc1[4 * j + 3]);
    }
}

// ---------------------------------------------------------------------------
// Kernel 2: in-degree histogram
// ---------------------------------------------------------------------------
__global__ void k_hist(const int* __restrict__ dst) {
    int e = blockIdx.x * blockDim.x + threadIdx.x;
    if (e >= N_EDGES) return;
    atomicAdd(&g_count[dst[e]], 1);
}

// ---------------------------------------------------------------------------
// Kernel 3a/3b/3c: hierarchical exclusive scan of g_count -> g_off, g_cur
// ---------------------------------------------------------------------------
__global__ __launch_bounds__(SCAN_B) void k_bsum() {
    __shared__ int sh[SCAN_B];
    int i = blockIdx.x * SCAN_B + threadIdx.x;
    sh[threadIdx.x] = (i < N_NODES) ? g_count[i] : 0;
    __syncthreads();
    for (int off = SCAN_B / 2; off > 0; off >>= 1) {
        if (threadIdx.x < off) sh[threadIdx.x] += sh[threadIdx.x + off];
        __syncthreads();
    }
    if (threadIdx.x == 0) g_bsum[blockIdx.x] = sh[0];
}

__global__ __launch_bounds__(512) void k_sscan() {
    __shared__ int sh[512];
    int t = threadIdx.x;
    sh[t] = (t < NB) ? g_bsum[t] : 0;
    __syncthreads();
    for (int off = 1; off < 512; off <<= 1) {
        int v = (t >= off) ? sh[t - off] : 0;
        __syncthreads();
        sh[t] += v;
        __syncthreads();
    }
    if (t < NB) g_bbase[t] = (t == 0) ? 0 : sh[t - 1];
}

__global__ __launch_bounds__(SCAN_B) void k_off() {
    __shared__ int sh[SCAN_B];
    int i = blockIdx.x * SCAN_B + threadIdx.x;
    int t = threadIdx.x;
    int c = (i < N_NODES) ? g_count[i] : 0;
    sh[t] = c;
    __syncthreads();
    for (int off = 1; off < SCAN_B; off <<= 1) {
        int v = (t >= off) ? sh[t - off] : 0;
        __syncthreads();
        sh[t] += v;
        __syncthreads();
    }
    if (i < N_NODES) {
        int excl = g_bbase[blockIdx.x] + sh[t] - c;
        g_off[i] = excl;
        g_cur[i] = excl;
    }
}

// ---------------------------------------------------------------------------
// Kernel 4: edge scatter — exp(leakyrelu(el[src]+er[dst])) per head,
// pack (src, x0, x1, x2) grouped by dst.
// Max-subtraction skipped: |e| <= ~4, softmax shift-invariant (fp32-safe).
// ---------------------------------------------------------------------------
__global__ void k_scatter(const int* __restrict__ src, const int* __restrict__ dst) {
    int e = blockIdx.x * blockDim.x + threadIdx.x;
    if (e >= N_EDGES) return;
    int s = src[e], d = dst[e];
    float4 L = g_el[s];
    float4 R = g_er[d];
    float v0 = L.x + R.x, v1 = L.y + R.y, v2 = L.z + R.z;
    v0 = v0 > 0.f ? v0 : NEG_SLOPE * v0;
    v1 = v1 > 0.f ? v1 : NEG_SLOPE * v1;
    v2 = v2 > 0.f ? v2 : NEG_SLOPE * v2;
    float x0 = __expf(v0), x1 = __expf(v1), x2 = __expf(v2);
    int pos = atomicAdd(&g_cur[d], 1);
    g_edge[pos] = make_float4(__int_as_float(s), x0, x1, x2);
}

// ---------------------------------------------------------------------------
// Kernel 5: per-dst aggregation, 48 threads/node. 2-edge unroll with
// independent accumulator pairs to double per-thread MLP against L2 latency.
// ---------------------------------------------------------------------------
__global__ __launch_bounds__(192) void k_agg(const float* __restrict__ lin,
                                             float* __restrict__ out) {
    int d = blockIdx.x * 4 + threadIdx.y;
    if (d >= N_NODES) return;
    int c = threadIdx.x;        // 0..47
    int h = c >> 4;             // head index 0..2

    int beg = g_off[d];
    int cnt = g_count[d];
    int end = beg + cnt;

    float num0 = 0.f, den0 = 0.f, num1 = 0.f, den1 = 0.f;
    int p = beg;
    for (; p + 2 <= end; p += 2) {
        float4 pk0 = g_edge[p];
        float4 pk1 = g_edge[p + 1];
        int s0 = __float_as_int(pk0.x);
        int s1 = __float_as_int(pk1.x);
        float a0 = (h == 0) ? pk0.y : ((h == 1) ? pk0.z : pk0.w);
        float a1 = (h == 0) ? pk1.y : ((h == 1) ? pk1.z : pk1.w);
        float f0 = __ldg(&g_feat[s0 * HD + c]);
        float f1 = __ldg(&g_feat[s1 * HD + c]);
        num0 = fmaf(a0, f0, num0); den0 += a0;
        num1 = fmaf(a1, f1, num1); den1 += a1;
    }
    if (p < end) {
        float4 pk = g_edge[p];
        int s = __float_as_int(pk.x);
        float a = (h == 0) ? pk.y : ((h == 1) ? pk.z : pk.w);
        float f = __ldg(&g_feat[s * HD + c]);
        num0 = fmaf(a, f, num0); den0 += a;
    }
    float num = num0 + num1, den = den0 + den1;
    float msg = (cnt > 0) ? (num / den) : 0.f;
    float l = lin[d];
    float fd = g_feat[d * HD + c];
    out[d * HD + c] = (1.f - l) * msg + l * fd;
}

// ---------------------------------------------------------------------------
extern "C" void kernel_launch(void* const* d_in, const int* in_sizes, int n_in,
                              void* d_out, int out_size) {
    const float* x   = (const float*)d_in[0];
    const float* W   = (const float*)d_in[1];
    const float* al  = (const float*)d_in[2];
    const float* ar  = (const float*)d_in[3];
    const float* lin = (const float*)d_in[4];
    const int*   src = (const int*)d_in[5];
    const int*   dst = (const int*)d_in[6];
    float* out = (float*)d_out;

    k_init<<<(N_NODES + 255) / 256, 256>>>();
    k_gemm<<<(N_NODES + 255) / 256, 128>>>(x, W, al, ar);
    k_hist<<<(N_EDGES + 255) / 256, 256>>>(dst);
    k_bsum<<<NB, SCAN_B>>>();
    k_sscan<<<1, 512>>>();
    k_off<<<NB, SCAN_B>>>();
    k_scatter<<<(N_EDGES + 255) / 256, 256>>>(src, dst);

    dim3 aggBlock(48, 4);
    k_agg<<<(N_NODES + 3) / 4, aggBlock>>>(lin, out);
}